// round 1
// baseline (speedup 1.0000x reference)
#include <cuda_runtime.h>

// ---------------------------------------------------------------------------
// CombinedGoalObsNetwork: GINEConv(2M edges) -> MLP -> GINConv(1M edges) -> MLP -> head
// F = 64 features everywhere.
// ---------------------------------------------------------------------------

#define F64 64
#define NTASK_MAX  32768
#define NACT_MAX   32768

// Scratch (allocation-free rule: __device__ globals). 16B aligned for float4/red.v4.
__device__ __align__(16) float g_h_task[NTASK_MAX * F64];  // x_task + agg (GINE)
__device__ __align__(16) float g_tmp   [NTASK_MAX * F64];  // hidden activations
__device__ __align__(16) float g_x1    [NTASK_MAX * F64];  // task embeddings after MLP1
__device__ __align__(16) float g_h2    [NACT_MAX  * F64];  // x_actor + agg2 (GIN)

// ---------------------------------------------------------------------------
// Init: h_task = x_task ; h2 = x_actor   (so scatter-adds land on the residual)
// ---------------------------------------------------------------------------
__global__ void init_kernel(const float* __restrict__ x_task,
                            const float* __restrict__ x_actor,
                            int n_task, int n_actor)
{
    int tot = gridDim.x * blockDim.x;
    int tid = blockIdx.x * blockDim.x + threadIdx.x;
    int nt4 = n_task * (F64 / 4);
    int na4 = n_actor * (F64 / 4);
    const float4* xt = (const float4*)x_task;
    const float4* xa = (const float4*)x_actor;
    float4* ht = (float4*)g_h_task;
    float4* h2 = (float4*)g_h2;
    for (int i = tid; i < nt4; i += tot) ht[i] = xt[i];
    for (int i = tid; i < na4; i += tot) h2[i] = xa[i];
}

// ---------------------------------------------------------------------------
// Vectorized 16B float reduction (sm_90+): one L2 RED op per 4 features.
// ---------------------------------------------------------------------------
__device__ __forceinline__ void red_add_v4(float* p, float4 v)
{
    asm volatile("red.global.add.v4.f32 [%0], {%1,%2,%3,%4};"
                 :: "l"(p), "f"(v.x), "f"(v.y), "f"(v.z), "f"(v.w)
                 : "memory");
}

// ---------------------------------------------------------------------------
// GINEConv edge kernel: 16 lanes per edge, 4 feats (float4) per lane.
//   msg = relu(x_state[src] + ea0*We[0,:] + ea1*We[1,:] + be)
//   h_task[dst] += msg   (red.v4)
// ---------------------------------------------------------------------------
__global__ void edge_gine_kernel(const float* __restrict__ x_state,
                                 const float* __restrict__ edge_attr,
                                 const float* __restrict__ We,
                                 const float* __restrict__ be,
                                 const int*   __restrict__ src,
                                 const int*   __restrict__ dst,
                                 int E)
{
    const int lane = threadIdx.x & 15;
    // Per-lane weight slice, loaded once (grid-stride persistent loop).
    const float4 w0 = __ldg((const float4*)We + lane);          // We[0][4l..4l+3]
    const float4 w1 = __ldg((const float4*)(We + F64) + lane);  // We[1][...]
    const float4 bb = __ldg((const float4*)be + lane);

    int g  = (blockIdx.x * blockDim.x + threadIdx.x) >> 4;
    int gs = (gridDim.x * blockDim.x) >> 4;

    #pragma unroll 2
    for (int e = g; e < E; e += gs) {
        const int s = __ldg(src + e);
        const int d = __ldg(dst + e);
        const float2 a = __ldg((const float2*)edge_attr + e);
        const float4 x = __ldg((const float4*)(x_state + (size_t)s * F64) + lane);
        float4 v;
        v.x = fmaxf(fmaf(a.x, w0.x, fmaf(a.y, w1.x, x.x + bb.x)), 0.f);
        v.y = fmaxf(fmaf(a.x, w0.y, fmaf(a.y, w1.y, x.y + bb.y)), 0.f);
        v.z = fmaxf(fmaf(a.x, w0.z, fmaf(a.y, w1.z, x.z + bb.z)), 0.f);
        v.w = fmaxf(fmaf(a.x, w0.w, fmaf(a.y, w1.w, x.w + bb.w)), 0.f);
        red_add_v4(g_h_task + (size_t)d * F64 + lane * 4, v);
    }
}

// ---------------------------------------------------------------------------
// GINConv edge kernel: pure gather + scatter-add of x1 rows.
// ---------------------------------------------------------------------------
__global__ void edge_gin_kernel(const int* __restrict__ src,
                                const int* __restrict__ dst,
                                int E)
{
    const int lane = threadIdx.x & 15;
    int g  = (blockIdx.x * blockDim.x + threadIdx.x) >> 4;
    int gs = (gridDim.x * blockDim.x) >> 4;

    #pragma unroll 2
    for (int e = g; e < E; e += gs) {
        const int s = __ldg(src + e);
        const int d = __ldg(dst + e);
        const float4 v = *((const float4*)(g_x1 + (size_t)s * F64) + lane);
        red_add_v4(g_h2 + (size_t)d * F64 + lane * 4, v);
    }
}

// ---------------------------------------------------------------------------
// Dense 64x64 layer, thread-per-row. W (16KB) + bias in SMEM (broadcast LDS).
// out[row, :] = maybe_relu(in[row, :] @ W + b)
// f-blocked (16 outputs per pass); input row re-read per block (L1-resident).
// ---------------------------------------------------------------------------
__global__ void gemm64_kernel(const float* __restrict__ in,
                              const float* __restrict__ W,
                              const float* __restrict__ b,
                              float* __restrict__ out,
                              int n, int do_relu)
{
    __shared__ float sW[F64 * F64];
    __shared__ float sb[F64];
    for (int i = threadIdx.x; i < F64 * F64; i += blockDim.x) sW[i] = W[i];
    if (threadIdx.x < F64) sb[threadIdx.x] = b[threadIdx.x];
    __syncthreads();

    const int row = blockIdx.x * blockDim.x + threadIdx.x;
    if (row >= n) return;

    const float4* hp = (const float4*)(in + (size_t)row * F64);
    float4* op = (float4*)(out + (size_t)row * F64);

    for (int fb = 0; fb < 4; fb++) {
        float acc[16];
        #pragma unroll
        for (int j = 0; j < 16; j++) acc[j] = sb[fb * 16 + j];

        #pragma unroll 4
        for (int k4 = 0; k4 < 16; k4++) {
            const float4 hv = __ldg(hp + k4);
            const float* wb = &sW[(k4 * 4) * F64 + fb * 16];
            #pragma unroll
            for (int j4 = 0; j4 < 4; j4++) {
                float4 w;
                w = *(const float4*)(wb + 0 * F64 + j4 * 4);
                acc[4*j4+0] = fmaf(hv.x, w.x, acc[4*j4+0]);
                acc[4*j4+1] = fmaf(hv.x, w.y, acc[4*j4+1]);
                acc[4*j4+2] = fmaf(hv.x, w.z, acc[4*j4+2]);
                acc[4*j4+3] = fmaf(hv.x, w.w, acc[4*j4+3]);
                w = *(const float4*)(wb + 1 * F64 + j4 * 4);
                acc[4*j4+0] = fmaf(hv.y, w.x, acc[4*j4+0]);
                acc[4*j4+1] = fmaf(hv.y, w.y, acc[4*j4+1]);
                acc[4*j4+2] = fmaf(hv.y, w.z, acc[4*j4+2]);
                acc[4*j4+3] = fmaf(hv.y, w.w, acc[4*j4+3]);
                w = *(const float4*)(wb + 2 * F64 + j4 * 4);
                acc[4*j4+0] = fmaf(hv.z, w.x, acc[4*j4+0]);
                acc[4*j4+1] = fmaf(hv.z, w.y, acc[4*j4+1]);
                acc[4*j4+2] = fmaf(hv.z, w.z, acc[4*j4+2]);
                acc[4*j4+3] = fmaf(hv.z, w.w, acc[4*j4+3]);
                w = *(const float4*)(wb + 3 * F64 + j4 * 4);
                acc[4*j4+0] = fmaf(hv.w, w.x, acc[4*j4+0]);
                acc[4*j4+1] = fmaf(hv.w, w.y, acc[4*j4+1]);
                acc[4*j4+2] = fmaf(hv.w, w.z, acc[4*j4+2]);
                acc[4*j4+3] = fmaf(hv.w, w.w, acc[4*j4+3]);
            }
        }

        #pragma unroll
        for (int i = 0; i < 4; i++) {
            float4 v = make_float4(acc[4*i+0], acc[4*i+1], acc[4*i+2], acc[4*i+3]);
            if (do_relu) {
                v.x = fmaxf(v.x, 0.f); v.y = fmaxf(v.y, 0.f);
                v.z = fmaxf(v.z, 0.f); v.w = fmaxf(v.w, 0.f);
            }
            op[fb * 4 + i] = v;
        }
    }
}

// ---------------------------------------------------------------------------
// Head: out[row] = t[row,:] @ W2b + b2b   (64 -> 1)
// ---------------------------------------------------------------------------
__global__ void logits_kernel(const float* __restrict__ tin,
                              const float* __restrict__ W2b,
                              const float* __restrict__ b2b,
                              float* __restrict__ out,
                              int n)
{
    __shared__ float sw[F64];
    if (threadIdx.x < F64) sw[threadIdx.x] = W2b[threadIdx.x];
    __syncthreads();

    const int row = blockIdx.x * blockDim.x + threadIdx.x;
    if (row >= n) return;

    const float4* tp = (const float4*)(tin + (size_t)row * F64);
    float s = __ldg(b2b);
    #pragma unroll
    for (int i = 0; i < 16; i++) {
        const float4 v = __ldg(tp + i);
        s = fmaf(v.x, sw[4*i+0], s);
        s = fmaf(v.y, sw[4*i+1], s);
        s = fmaf(v.z, sw[4*i+2], s);
        s = fmaf(v.w, sw[4*i+3], s);
    }
    out[row] = s;
}

// ---------------------------------------------------------------------------
static inline int imin(int a, int b) { return a < b ? a : b; }

extern "C" void kernel_launch(void* const* d_in, const int* in_sizes, int n_in,
                              void* d_out, int out_size)
{
    const float* x_state   = (const float*)d_in[0];
    const float* x_task    = (const float*)d_in[1];
    const float* x_actor   = (const float*)d_in[2];
    const float* edge_attr = (const float*)d_in[3];
    const float* We  = (const float*)d_in[4];
    const float* be  = (const float*)d_in[5];
    const float* W1a = (const float*)d_in[6];
    const float* b1a = (const float*)d_in[7];
    const float* W1b = (const float*)d_in[8];
    const float* b1b = (const float*)d_in[9];
    const float* W2a = (const float*)d_in[10];
    const float* b2a = (const float*)d_in[11];
    const float* W2b = (const float*)d_in[12];
    const float* b2b = (const float*)d_in[13];
    const int* src_st = (const int*)d_in[14];
    const int* dst_st = (const int*)d_in[15];
    const int* src_ta = (const int*)d_in[16];
    const int* dst_ta = (const int*)d_in[17];

    const int n_task  = in_sizes[1] / F64;
    const int n_actor = in_sizes[2] / F64;
    const int E_st = in_sizes[14];
    const int E_ta = in_sizes[16];

    float *p_h_task, *p_tmp, *p_x1, *p_h2;
    cudaGetSymbolAddress((void**)&p_h_task, g_h_task);
    cudaGetSymbolAddress((void**)&p_tmp,    g_tmp);
    cudaGetSymbolAddress((void**)&p_x1,     g_x1);
    cudaGetSymbolAddress((void**)&p_h2,     g_h2);

    // 1) residual init
    init_kernel<<<1024, 256>>>(x_task, x_actor, n_task, n_actor);

    // 2) GINEConv message + scatter (16 lanes/edge)
    {
        int blocks = imin((E_st * 16 + 255) / 256, 148 * 48);
        edge_gine_kernel<<<blocks, 256>>>(x_state, edge_attr, We, be,
                                          src_st, dst_st, E_st);
    }

    // 3) task MLP: x1 = relu(h @ W1a + b1a) @ W1b + b1b
    {
        int gb = (n_task + 255) / 256;
        gemm64_kernel<<<gb, 256>>>(p_h_task, W1a, b1a, p_tmp, n_task, 1);
        gemm64_kernel<<<gb, 256>>>(p_tmp,    W1b, b1b, p_x1,  n_task, 0);
    }

    // 4) GINConv gather + scatter
    {
        int blocks = imin((E_ta * 16 + 255) / 256, 148 * 48);
        edge_gin_kernel<<<blocks, 256>>>(src_ta, dst_ta, E_ta);
    }

    // 5) actor MLP + head
    {
        int ga = (n_actor + 255) / 256;
        gemm64_kernel<<<ga, 256>>>(p_h2, W2a, b2a, p_tmp, n_actor, 1);
        logits_kernel<<<ga, 256>>>(p_tmp, W2b, b2b, (float*)d_out, n_actor);
    }
}